// round 3
// baseline (speedup 1.0000x reference)
#include <cuda_runtime.h>
#include <math.h>

#define NN 6144
#define NV 3
#define NF 512
#define NK 10
#define KP 11
#define NITERS 2
#define BN_EPS 1e-5f

// ---------------- scratch (device globals, no allocation) ----------------
__device__ float g_proj[NV * NN * NK];
__device__ float g_Y[NV * NN * NK];
__device__ float g_h[NN * NK];
__device__ float g_z[NN * NK];
__device__ float g_stats[NITERS * 2 * NK]; // [t][sum|sumsq][k]

// ---------------- packed f32x2 helpers ----------------
__device__ __forceinline__ unsigned long long pack2(float a, float b) {
    unsigned long long r;
    asm("mov.b64 %0, {%1, %2};" : "=l"(r) : "f"(a), "f"(b));
    return r;
}
__device__ __forceinline__ void ffma2(unsigned long long& d, unsigned long long a, unsigned long long b) {
    asm("fma.rn.f32x2 %0, %1, %2, %0;" : "+l"(d) : "l"(a), "l"(b));
}
__device__ __forceinline__ float2 unpack2(unsigned long long v) {
    float2 r;
    asm("mov.b64 {%0, %1}, %2;" : "=f"(r.x), "=f"(r.y) : "l"(v));
    return r;
}

// ---------------- kernel 0: zero stats ----------------
__global__ void zero_stats_kernel() {
    int i = threadIdx.x;
    if (i < NITERS * 2 * NK) g_stats[i] = 0.0f;
}

// ---------------- kernel 1: proj[v,n,k] = sum_f X[v,n,f] U[v,f,k] ----------------
__global__ __launch_bounds__(256) void proj_kernel(const float* __restrict__ feat,
                                                   const float* __restrict__ U) {
    __shared__ float Ut[NK][NF];
    int tid = threadIdx.x, lane = tid & 31, wid = tid >> 5;
    int bx = blockIdx.x;
    int v = bx / (NN / 8);
    int rb = bx % (NN / 8);

    for (int i = tid; i < NF * NK; i += 256) {
        int f = i / NK, k = i % NK;
        Ut[k][f] = U[(size_t)v * NF * NK + i];
    }
    __syncthreads();

    int n = rb * 8 + wid;
    const float4* xr = (const float4*)(feat + ((size_t)v * NN + n) * NF);
    float acc[NK];
#pragma unroll
    for (int k = 0; k < NK; k++) acc[k] = 0.0f;

#pragma unroll
    for (int it = 0; it < NF / 128; it++) {
        int f4 = it * 32 + lane;
        float4 x = xr[f4];
#pragma unroll
        for (int k = 0; k < NK; k++) {
            float4 u = *(const float4*)&Ut[k][f4 * 4];
            acc[k] = fmaf(x.x, u.x, acc[k]);
            acc[k] = fmaf(x.y, u.y, acc[k]);
            acc[k] = fmaf(x.z, u.z, acc[k]);
            acc[k] = fmaf(x.w, u.w, acc[k]);
        }
    }
#pragma unroll
    for (int k = 0; k < NK; k++)
        for (int s = 16; s; s >>= 1) acc[k] += __shfl_xor_sync(0xffffffffu, acc[k], s);

    if (lane == 0) {
        float* pr = g_proj + ((size_t)v * NN + n) * NK;
#pragma unroll
        for (int k = 0; k < NK; k++) pr[k] = acc[k];
    }
}

// ---------------- kernel 2: Y[v,n,k] = sum_m L[v,n,m] * z[m,k] ----------------
// 256 threads (8 warps), 8 rows/warp -> 64 rows/block, grid = 288, 2 CTAs/SM.
// Software-pipelined: next 8-row batch of L loads in flight while computing current.
#define M_CHUNK 1024
#define GEMV_THREADS 256
#define RPW 8
#define ROWS_PER_BLOCK 64   // 8 warps * 8 rows
#define NJ (M_CHUNK / 32)   // 32 j-steps per chunk

__global__ __launch_bounds__(GEMV_THREADS, 2) void gemv_kernel(const float* __restrict__ lap,
                                                               const float* __restrict__ z_ext,
                                                               int use_ext) {
    const float* zsrc = use_ext ? z_ext : g_z;
    __shared__ float zs[M_CHUNK * KP];

    int tid = threadIdx.x, lane = tid & 31, wid = tid >> 5;
    int bx = blockIdx.x;
    int v = bx / (NN / ROWS_PER_BLOCK);
    int rb = bx % (NN / ROWS_PER_BLOCK);
    int n0 = rb * ROWS_PER_BLOCK + wid * RPW;

    const float* Lbase = lap + ((size_t)v * NN + n0) * (size_t)NN;

    unsigned long long acc[RPW][5];
#pragma unroll
    for (int r = 0; r < RPW; r++)
#pragma unroll
        for (int p = 0; p < 5; p++) acc[r][p] = 0ull;

    for (int c = 0; c < NN; c += M_CHUNK) {
        __syncthreads();
        for (int i = tid; i < M_CHUNK * NK; i += GEMV_THREADS)
            zs[(i / NK) * KP + (i % NK)] = zsrc[c * NK + i];
        __syncthreads();

        const float* lptr = Lbase + c + lane;

        float a[RPW], b[RPW];
#pragma unroll
        for (int r = 0; r < RPW; r++) a[r] = __ldcs(lptr + (size_t)r * NN);

#pragma unroll 1
        for (int it = 0; it < NJ - 1; it++) {
            // prefetch next j-step (front-batched 8 LDGs)
#pragma unroll
            for (int r = 0; r < RPW; r++) b[r] = __ldcs(lptr + (it + 1) * 32 + (size_t)r * NN);

            const float* zr = zs + (it * 32 + lane) * KP;
            unsigned long long zp[5];
#pragma unroll
            for (int p = 0; p < 5; p++) zp[p] = pack2(zr[2 * p], zr[2 * p + 1]);
#pragma unroll
            for (int r = 0; r < RPW; r++) {
                unsigned long long d = pack2(a[r], a[r]);
#pragma unroll
                for (int p = 0; p < 5; p++) ffma2(acc[r][p], d, zp[p]);
            }
#pragma unroll
            for (int r = 0; r < RPW; r++) a[r] = b[r];
        }
        {   // epilogue j-step
            const float* zr = zs + ((NJ - 1) * 32 + lane) * KP;
            unsigned long long zp[5];
#pragma unroll
            for (int p = 0; p < 5; p++) zp[p] = pack2(zr[2 * p], zr[2 * p + 1]);
#pragma unroll
            for (int r = 0; r < RPW; r++) {
                unsigned long long d = pack2(a[r], a[r]);
#pragma unroll
                for (int p = 0; p < 5; p++) ffma2(acc[r][p], d, zp[p]);
            }
        }
    }

#pragma unroll
    for (int r = 0; r < RPW; r++) {
        float vals[NK];
#pragma unroll
        for (int p = 0; p < 5; p++) {
            float2 f = unpack2(acc[r][p]);
            vals[2 * p] = f.x;
            vals[2 * p + 1] = f.y;
        }
#pragma unroll
        for (int k = 0; k < NK; k++)
            for (int s = 16; s; s >>= 1) vals[k] += __shfl_xor_sync(0xffffffffu, vals[k], s);
        if (lane == 0) {
            float* yr = g_Y + ((size_t)v * NN + n0 + r) * NK;
#pragma unroll
            for (int k = 0; k < NK; k++) yr[k] = vals[k];
        }
    }
}

// ---------------- kernel 3: softplus evidences + DS combine + BN stats ----------------
__device__ __forceinline__ float softplusf(float x) {
    return fmaxf(x, 0.0f) + __logf(1.0f + __expf(-fabsf(x)));
}

__device__ __forceinline__ void ds_comb(float* a1, const float* a2) {
    float S1 = 0.0f, S2 = 0.0f;
#pragma unroll
    for (int k = 0; k < NK; k++) { S1 += a1[k]; S2 += a2[k]; }
    float i1 = 1.0f / S1, i2 = 1.0f / S2;
    float u1 = (float)NK * i1, u2 = (float)NK * i2;
    float b1[NK], b2[NK];
    float sb1 = 0.0f, sb2 = 0.0f, dot = 0.0f;
#pragma unroll
    for (int k = 0; k < NK; k++) {
        b1[k] = (a1[k] - 1.0f) * i1;
        b2[k] = (a2[k] - 1.0f) * i2;
        sb1 += b1[k];
        sb2 += b2[k];
        dot += b1[k] * b2[k];
    }
    float C = sb1 * sb2 - dot;
    float invd = 1.0f / (1.0f - C);
    float Sn = (float)NK * (1.0f - C) / (u1 * u2);
#pragma unroll
    for (int k = 0; k < NK; k++)
        a1[k] = (b1[k] * b2[k] + b1[k] * u2 + b2[k] * u1) * invd * Sn + 1.0f;
}

#define CMB_THREADS 64
__global__ __launch_bounds__(CMB_THREADS) void combine_kernel(const float* __restrict__ z_ext,
                                                              int use_ext, int t) {
    const float* zsrc = use_ext ? z_ext : g_z;
    int n = blockIdx.x * CMB_THREADS + threadIdx.x; // grid exactly covers N
    int lane = threadIdx.x & 31;

    float zn[NK];
#pragma unroll
    for (int k = 0; k < NK; k++) zn[k] = zsrc[n * NK + k];

    float ac[NK];
    {
        const float* yr = g_Y + (size_t)n * NK;
        const float* pr = g_proj + (size_t)n * NK;
#pragma unroll
        for (int k = 0; k < NK; k++) ac[k] = softplusf(zn[k] - yr[k] + pr[k]) + 1.0f;
    }
#pragma unroll
    for (int v = 1; v < NV; v++) {
        float av[NK];
        const float* yr = g_Y + ((size_t)v * NN + n) * NK;
        const float* pr = g_proj + ((size_t)v * NN + n) * NK;
#pragma unroll
        for (int k = 0; k < NK; k++) av[k] = softplusf(zn[k] - yr[k] + pr[k]) + 1.0f;
        ds_comb(ac, av);
    }

    float sq[NK];
#pragma unroll
    for (int k = 0; k < NK; k++) {
        g_h[n * NK + k] = ac[k];
        sq[k] = ac[k] * ac[k];
    }

#pragma unroll
    for (int k = 0; k < NK; k++) {
        for (int s = 16; s; s >>= 1) {
            ac[k] += __shfl_xor_sync(0xffffffffu, ac[k], s);
            sq[k] += __shfl_xor_sync(0xffffffffu, sq[k], s);
        }
    }
    __shared__ float sh[2 * NK];
    if (threadIdx.x < 2 * NK) sh[threadIdx.x] = 0.0f;
    __syncthreads();
    if (lane == 0) {
#pragma unroll
        for (int k = 0; k < NK; k++) {
            atomicAdd(&sh[k], ac[k]);
            atomicAdd(&sh[NK + k], sq[k]);
        }
    }
    __syncthreads();
    if (threadIdx.x < 2 * NK)
        atomicAdd(&g_stats[t * 2 * NK + threadIdx.x], sh[threadIdx.x]);
}

// ---------------- kernel 4: BatchNorm + SELU soft-threshold ----------------
__device__ __forceinline__ float seluf(float x) {
    const float sc = 1.0507009873554805f, al = 1.6732632423543772f;
    return x > 0.0f ? sc * x : sc * al * (__expf(x) - 1.0f);
}

__global__ __launch_bounds__(256) void bn_selu_kernel(float* __restrict__ out,
                                                      const float* __restrict__ gamma,
                                                      const float* __restrict__ beta,
                                                      const float* __restrict__ theta,
                                                      int t) {
    int i = blockIdx.x * 256 + threadIdx.x; // grid exactly covers N*K
    int k = i % NK;
    float mu = g_stats[t * 2 * NK + k] * (1.0f / NN);
    float ms = g_stats[t * 2 * NK + NK + k] * (1.0f / NN);
    float var = ms - mu * mu;
    float inv = rsqrtf(var + BN_EPS);
    float hn = (g_h[i] - mu) * inv * gamma[k] + beta[k];
    float th = theta[0];
    float z = seluf(hn - th) - seluf(-hn - th);
    out[(size_t)t * NN * NK + i] = z;
    g_z[i] = z;
}

// ---------------- launcher ----------------
extern "C" void kernel_launch(void* const* d_in, const int* in_sizes, int n_in,
                              void* d_out, int out_size) {
    (void)in_sizes; (void)n_in; (void)out_size;
    const float* feat  = (const float*)d_in[0]; // [V,N,F]
    const float* lap   = (const float*)d_in[1]; // [V,N,N]
    const float* z0    = (const float*)d_in[2]; // [N,K]
    const float* U     = (const float*)d_in[3]; // [V,F,K]
    const float* theta = (const float*)d_in[4]; // [1]
    const float* gamma = (const float*)d_in[5]; // [K]
    const float* beta  = (const float*)d_in[6]; // [K]
    float* out = (float*)d_out;                 // [2,N,K]

    zero_stats_kernel<<<1, 64>>>();
    proj_kernel<<<NV * (NN / 8), 256>>>(feat, U);

    for (int t = 0; t < NITERS; t++) {
        int use_ext = (t == 0) ? 1 : 0;
        gemv_kernel<<<NV * (NN / ROWS_PER_BLOCK), GEMV_THREADS>>>(lap, z0, use_ext);
        combine_kernel<<<NN / CMB_THREADS, CMB_THREADS>>>(z0, use_ext, t);
        bn_selu_kernel<<<(NN * NK) / 256, 256>>>(out, gamma, beta, theta, t);
    }
}

// round 4
// speedup vs baseline: 1.3385x; 1.3385x over previous
#include <cuda_runtime.h>
#include <math.h>

#define NN 6144
#define NV 3
#define NF 512
#define NK 10
#define YP 12            // padded row stride for Y/proj/h/z scratch
#define NITERS 2
#define BN_EPS 1e-5f

#define M_CHUNK 1024
#define MQ 256           // M_CHUNK/4
#define MQP 258          // padded
#define NCHUNK (NN / M_CHUNK)          // 6
#define ITS_PER_CHUNK (M_CHUNK / 128)  // 8
#define NSTEPS (NN / 128)              // 48

// ---------------- scratch (device globals, no allocation) ----------------
__device__ float g_proj[NV * NN * YP];
__device__ float g_Y[NV * NN * YP];
__device__ float g_h[NN * YP];
__device__ float g_z[NN * YP];
__device__ float g_stats[NITERS * 2 * NK];

// ---------------- packed f32x2 helpers ----------------
__device__ __forceinline__ unsigned long long pack2(float a, float b) {
    unsigned long long r;
    asm("mov.b64 %0, {%1, %2};" : "=l"(r) : "f"(a), "f"(b));
    return r;
}
__device__ __forceinline__ void ffma2(unsigned long long& d, unsigned long long a, unsigned long long b) {
    asm("fma.rn.f32x2 %0, %1, %2, %0;" : "+l"(d) : "l"(a), "l"(b));
}
__device__ __forceinline__ float2 unpack2(unsigned long long v) {
    float2 r;
    asm("mov.b64 {%0, %1}, %2;" : "=f"(r.x), "=f"(r.y) : "l"(v));
    return r;
}

// ---------------- kernel 1: proj (also zeroes stats) ----------------
__global__ __launch_bounds__(256) void proj_kernel(const float* __restrict__ feat,
                                                   const float* __restrict__ U) {
    __shared__ float Ut[NK][NF];
    int tid = threadIdx.x, lane = tid & 31, wid = tid >> 5;
    int bx = blockIdx.x;
    if (bx == 0 && tid < NITERS * 2 * NK) g_stats[tid] = 0.0f;

    int v = bx / (NN / 8);
    int rb = bx % (NN / 8);

    for (int i = tid; i < NF * NK; i += 256) {
        int f = i / NK, k = i % NK;
        Ut[k][f] = U[(size_t)v * NF * NK + i];
    }
    __syncthreads();

    int n = rb * 8 + wid;
    const float4* xr = (const float4*)(feat + ((size_t)v * NN + n) * NF);
    float acc[NK];
#pragma unroll
    for (int k = 0; k < NK; k++) acc[k] = 0.0f;

#pragma unroll
    for (int it = 0; it < NF / 128; it++) {
        int f4 = it * 32 + lane;
        float4 x = xr[f4];
#pragma unroll
        for (int k = 0; k < NK; k++) {
            float4 u = *(const float4*)&Ut[k][f4 * 4];
            acc[k] = fmaf(x.x, u.x, acc[k]);
            acc[k] = fmaf(x.y, u.y, acc[k]);
            acc[k] = fmaf(x.z, u.z, acc[k]);
            acc[k] = fmaf(x.w, u.w, acc[k]);
        }
    }
#pragma unroll
    for (int k = 0; k < NK; k++)
        for (int s = 16; s; s >>= 1) acc[k] += __shfl_xor_sync(0xffffffffu, acc[k], s);

    if (lane == 0) {
        float* pr = g_proj + ((size_t)v * NN + n) * YP;
#pragma unroll
        for (int k = 0; k < NK; k++) pr[k] = acc[k];
    }
}

// ---------------- kernel 2: Y[v,n,k] = sum_m L[v,n,m] * z[m,k] ----------------
// 256 threads, 1 CTA/SM. 8 rows/warp, LDG.128 on L (4 KB in flight / warp).
// z chunk stored as zt[(q*5+p)*MQP + m] u64 (k-pair packed) -> LDS.64 conflict-free,
// loads feed FFMA2 directly.
#define GEMV_THREADS 256
#define RPW 8
#define ROWS_PER_BLOCK 64

__global__ __launch_bounds__(GEMV_THREADS, 1) void gemv_kernel(const float* __restrict__ lap,
                                                               const float* __restrict__ z_ext,
                                                               int use_ext) {
    const float* zsrc = use_ext ? z_ext : g_z;
    const int zstr = use_ext ? NK : YP;
    __shared__ unsigned long long zt[4 * 5 * MQP];

    int tid = threadIdx.x, lane = tid & 31, wid = tid >> 5;
    int bx = blockIdx.x;
    int v = bx / (NN / ROWS_PER_BLOCK);
    int rb = bx % (NN / ROWS_PER_BLOCK);
    int n0 = rb * ROWS_PER_BLOCK + wid * RPW;

    const float4* L4 = (const float4*)(lap + ((size_t)v * NN + n0) * (size_t)NN);
    const int ROW4 = NN / 4;

    unsigned long long acc[RPW][5];
#pragma unroll
    for (int r = 0; r < RPW; r++)
#pragma unroll
        for (int p = 0; p < 5; p++) acc[r][p] = 0ull;

    float4 a[RPW], b[RPW];
    // preload step 0 (overlaps first fill)
#pragma unroll
    for (int r = 0; r < RPW; r++) a[r] = __ldcs(L4 + (size_t)r * ROW4 + lane);

    for (int c = 0; c < NCHUNK; c++) {
        __syncthreads();
        // fill zt: p-major so STS spreads banks; global z reads hit L2
        for (int i = tid; i < 5 * M_CHUNK; i += GEMV_THREADS) {
            int p = i >> 10;          // 0..4
            int j = i & (M_CHUNK - 1);
            const float2* zp2 = (const float2*)(zsrc + (size_t)(c * M_CHUNK + j) * zstr + 2 * p);
            float2 zv = *zp2;
            zt[((j & 3) * 5 + p) * MQP + (j >> 2)] = pack2(zv.x, zv.y);
        }
        __syncthreads();

#pragma unroll 2
        for (int it = 0; it < ITS_PER_CHUNK; it++) {
            int s = c * ITS_PER_CHUNK + it;
            int sp = (s + 1 < NSTEPS) ? s + 1 : (NSTEPS - 1);
            // prefetch next step's L (front-batched LDG.128 x8)
#pragma unroll
            for (int r = 0; r < RPW; r++)
                b[r] = __ldcs(L4 + (size_t)r * ROW4 + sp * 32 + lane);

            int mi = it * 32 + lane;
#pragma unroll
            for (int q = 0; q < 4; q++) {
                unsigned long long zq[5];
#pragma unroll
                for (int p = 0; p < 5; p++) zq[p] = zt[(q * 5 + p) * MQP + mi];
#pragma unroll
                for (int r = 0; r < RPW; r++) {
                    float av = (q == 0) ? a[r].x : (q == 1) ? a[r].y : (q == 2) ? a[r].z : a[r].w;
                    unsigned long long d = pack2(av, av);
#pragma unroll
                    for (int p = 0; p < 5; p++) ffma2(acc[r][p], d, zq[p]);
                }
            }
#pragma unroll
            for (int r = 0; r < RPW; r++) a[r] = b[r];
        }
    }

#pragma unroll
    for (int r = 0; r < RPW; r++) {
        float vals[NK];
#pragma unroll
        for (int p = 0; p < 5; p++) {
            float2 f = unpack2(acc[r][p]);
            vals[2 * p] = f.x;
            vals[2 * p + 1] = f.y;
        }
#pragma unroll
        for (int k = 0; k < NK; k++)
            for (int s = 16; s; s >>= 1) vals[k] += __shfl_xor_sync(0xffffffffu, vals[k], s);
        if (lane == 0) {
            float* yr = g_Y + ((size_t)v * NN + n0 + r) * YP;
#pragma unroll
            for (int k = 0; k < NK; k++) yr[k] = vals[k];
        }
    }
}

// ---------------- kernel 3: softplus evidences + DS combine + BN stats ----------------
__device__ __forceinline__ float softplusf(float x) {
    return fmaxf(x, 0.0f) + __logf(1.0f + __expf(-fabsf(x)));
}

__device__ __forceinline__ void ds_comb(float* a1, const float* a2) {
    float S1 = 0.0f, S2 = 0.0f;
#pragma unroll
    for (int k = 0; k < NK; k++) { S1 += a1[k]; S2 += a2[k]; }
    float i1 = 1.0f / S1, i2 = 1.0f / S2;
    float u1 = (float)NK * i1, u2 = (float)NK * i2;
    float b1[NK], b2[NK];
    float sb1 = 0.0f, sb2 = 0.0f, dot = 0.0f;
#pragma unroll
    for (int k = 0; k < NK; k++) {
        b1[k] = (a1[k] - 1.0f) * i1;
        b2[k] = (a2[k] - 1.0f) * i2;
        sb1 += b1[k];
        sb2 += b2[k];
        dot += b1[k] * b2[k];
    }
    float C = sb1 * sb2 - dot;
    float invd = 1.0f / (1.0f - C);
    float Sn = (float)NK * (1.0f - C) / (u1 * u2);
#pragma unroll
    for (int k = 0; k < NK; k++)
        a1[k] = (b1[k] * b2[k] + b1[k] * u2 + b2[k] * u1) * invd * Sn + 1.0f;
}

#define CMB_THREADS 64
__global__ __launch_bounds__(CMB_THREADS) void combine_kernel(const float* __restrict__ z_ext,
                                                              int use_ext, int t) {
    const float* zsrc = use_ext ? z_ext : g_z;
    const int zstr = use_ext ? NK : YP;
    int n = blockIdx.x * CMB_THREADS + threadIdx.x;
    int lane = threadIdx.x & 31;

    float zn[NK];
#pragma unroll
    for (int p = 0; p < 5; p++) {
        float2 zv = *(const float2*)(zsrc + (size_t)n * zstr + 2 * p);
        zn[2 * p] = zv.x;
        zn[2 * p + 1] = zv.y;
    }

    float ac[NK];
#pragma unroll
    for (int v = 0; v < NV; v++) {
        const float4* y4 = (const float4*)(g_Y + ((size_t)v * NN + n) * YP);
        const float4* p4 = (const float4*)(g_proj + ((size_t)v * NN + n) * YP);
        float yv[12], pv[12];
#pragma unroll
        for (int q = 0; q < 3; q++) {
            float4 yq = y4[q];
            float4 pq = p4[q];
            yv[4 * q] = yq.x; yv[4 * q + 1] = yq.y; yv[4 * q + 2] = yq.z; yv[4 * q + 3] = yq.w;
            pv[4 * q] = pq.x; pv[4 * q + 1] = pq.y; pv[4 * q + 2] = pq.z; pv[4 * q + 3] = pq.w;
        }
        float av[NK];
#pragma unroll
        for (int k = 0; k < NK; k++) av[k] = softplusf(zn[k] - yv[k] + pv[k]) + 1.0f;
        if (v == 0) {
#pragma unroll
            for (int k = 0; k < NK; k++) ac[k] = av[k];
        } else {
            ds_comb(ac, av);
        }
    }

    float sq[NK];
#pragma unroll
    for (int k = 0; k < NK; k++) {
        g_h[(size_t)n * YP + k] = ac[k];
        sq[k] = ac[k] * ac[k];
    }

#pragma unroll
    for (int k = 0; k < NK; k++) {
        for (int s = 16; s; s >>= 1) {
            ac[k] += __shfl_xor_sync(0xffffffffu, ac[k], s);
            sq[k] += __shfl_xor_sync(0xffffffffu, sq[k], s);
        }
    }
    __shared__ float sh[2 * NK];
    if (threadIdx.x < 2 * NK) sh[threadIdx.x] = 0.0f;
    __syncthreads();
    if (lane == 0) {
#pragma unroll
        for (int k = 0; k < NK; k++) {
            atomicAdd(&sh[k], ac[k]);
            atomicAdd(&sh[NK + k], sq[k]);
        }
    }
    __syncthreads();
    if (threadIdx.x < 2 * NK)
        atomicAdd(&g_stats[t * 2 * NK + threadIdx.x], sh[threadIdx.x]);
}

// ---------------- kernel 4: BatchNorm + SELU soft-threshold ----------------
__device__ __forceinline__ float seluf(float x) {
    const float sc = 1.0507009873554805f, al = 1.6732632423543772f;
    return x > 0.0f ? sc * x : sc * al * (__expf(x) - 1.0f);
}

__global__ __launch_bounds__(256) void bn_selu_kernel(float* __restrict__ out,
                                                      const float* __restrict__ gamma,
                                                      const float* __restrict__ beta,
                                                      const float* __restrict__ theta,
                                                      int t) {
    int i = blockIdx.x * 256 + threadIdx.x; // covers N*K
    int n = i / NK, k = i % NK;
    float mu = g_stats[t * 2 * NK + k] * (1.0f / NN);
    float ms = g_stats[t * 2 * NK + NK + k] * (1.0f / NN);
    float var = ms - mu * mu;
    float inv = rsqrtf(var + BN_EPS);
    float hn = (g_h[(size_t)n * YP + k] - mu) * inv * gamma[k] + beta[k];
    float th = theta[0];
    float z = seluf(hn - th) - seluf(-hn - th);
    out[(size_t)t * NN * NK + i] = z;
    g_z[(size_t)n * YP + k] = z;
}

// ---------------- launcher ----------------
extern "C" void kernel_launch(void* const* d_in, const int* in_sizes, int n_in,
                              void* d_out, int out_size) {
    (void)in_sizes; (void)n_in; (void)out_size;
    const float* feat  = (const float*)d_in[0]; // [V,N,F]
    const float* lap   = (const float*)d_in[1]; // [V,N,N]
    const float* z0    = (const float*)d_in[2]; // [N,K]
    const float* U     = (const float*)d_in[3]; // [V,F,K]
    const float* theta = (const float*)d_in[4]; // [1]
    const float* gamma = (const float*)d_in[5]; // [K]
    const float* beta  = (const float*)d_in[6]; // [K]
    float* out = (float*)d_out;                 // [2,N,K]

    proj_kernel<<<NV * (NN / 8), 256>>>(feat, U);

    for (int t = 0; t < NITERS; t++) {
        int use_ext = (t == 0) ? 1 : 0;
        gemv_kernel<<<NV * (NN / ROWS_PER_BLOCK), GEMV_THREADS>>>(lap, z0, use_ext);
        combine_kernel<<<NN / CMB_THREADS, CMB_THREADS>>>(z0, use_ext, t);
        bn_selu_kernel<<<(NN * NK) / 256, 256>>>(out, gamma, beta, theta, t);
    }
}

// round 5
// speedup vs baseline: 1.4278x; 1.0667x over previous
#include <cuda_runtime.h>
#include <math.h>

#define NN 6144
#define NV 3
#define NF 512
#define NK 10
#define YP 12            // padded row stride for Y/proj/z scratch
#define NITERS 2
#define BN_EPS 1e-5f

#define M_CHUNK 2048
#define MQ (M_CHUNK / 4)         // 512
#define MQP (MQ + 2)             // 514 (padded)
#define NCHUNK (NN / M_CHUNK)          // 3
#define ITS_PER_CHUNK (M_CHUNK / 128)  // 16
#define NSTEPS (NN / 128)              // 48

// ---------------- scratch (device globals, no allocation) ----------------
__device__ float g_proj[NV * NN * YP];
__device__ float g_Y[NV * NN * YP];
__device__ float g_z[NN * YP];
__device__ float g_stats[NITERS * 2 * NK];
__device__ int   g_cnt[NITERS];

// ---------------- packed f32x2 helpers ----------------
__device__ __forceinline__ unsigned long long pack2(float a, float b) {
    unsigned long long r;
    asm("mov.b64 %0, {%1, %2};" : "=l"(r) : "f"(a), "f"(b));
    return r;
}
__device__ __forceinline__ void ffma2(unsigned long long& d, unsigned long long a, unsigned long long b) {
    asm("fma.rn.f32x2 %0, %1, %2, %0;" : "+l"(d) : "l"(a), "l"(b));
}
__device__ __forceinline__ float2 unpack2(unsigned long long v) {
    float2 r;
    asm("mov.b64 {%0, %1}, %2;" : "=f"(r.x), "=f"(r.y) : "l"(v));
    return r;
}

// ---------------- kernel 1: proj (also zeroes stats + counters) ----------------
__global__ __launch_bounds__(256) void proj_kernel(const float* __restrict__ feat,
                                                   const float* __restrict__ U) {
    __shared__ float Ut[NK][NF];
    int tid = threadIdx.x, lane = tid & 31, wid = tid >> 5;
    int bx = blockIdx.x;
    if (bx == 0) {
        if (tid < NITERS * 2 * NK) g_stats[tid] = 0.0f;
        if (tid >= 64 && tid < 64 + NITERS) g_cnt[tid - 64] = 0;
    }

    int v = bx / (NN / 8);
    int rb = bx % (NN / 8);

    for (int i = tid; i < NF * NK; i += 256) {
        int f = i / NK, k = i % NK;
        Ut[k][f] = U[(size_t)v * NF * NK + i];
    }
    __syncthreads();

    int n = rb * 8 + wid;
    const float4* xr = (const float4*)(feat + ((size_t)v * NN + n) * NF);
    float acc[NK];
#pragma unroll
    for (int k = 0; k < NK; k++) acc[k] = 0.0f;

#pragma unroll
    for (int it = 0; it < NF / 128; it++) {
        int f4 = it * 32 + lane;
        float4 x = xr[f4];
#pragma unroll
        for (int k = 0; k < NK; k++) {
            float4 u = *(const float4*)&Ut[k][f4 * 4];
            acc[k] = fmaf(x.x, u.x, acc[k]);
            acc[k] = fmaf(x.y, u.y, acc[k]);
            acc[k] = fmaf(x.z, u.z, acc[k]);
            acc[k] = fmaf(x.w, u.w, acc[k]);
        }
    }
#pragma unroll
    for (int k = 0; k < NK; k++)
        for (int s = 16; s; s >>= 1) acc[k] += __shfl_xor_sync(0xffffffffu, acc[k], s);

    if (lane == 0) {
        float* pr = g_proj + ((size_t)v * NN + n) * YP;
#pragma unroll
        for (int k = 0; k < NK; k++) pr[k] = acc[k];
    }
}

// ---------------- kernel 2: Y[v,n,k] = sum_m L[v,n,m] * z[m,k] ----------------
// 256 threads, 1 CTA/SM, 8 rows/warp, LDG.128, depth-2 register pipeline
// (16 LDG.128 in flight / warp = 8 KB). z chunk packed as u64 k-pairs in smem.
#define GEMV_THREADS 256
#define RPW 8
#define ROWS_PER_BLOCK 64

__global__ __launch_bounds__(GEMV_THREADS, 1) void gemv_kernel(const float* __restrict__ lap,
                                                               const float* __restrict__ z_ext,
                                                               int use_ext) {
    const float* zsrc = use_ext ? z_ext : g_z;
    const int zstr = use_ext ? NK : YP;
    extern __shared__ unsigned long long zt[];   // [4*5*MQP]

    int tid = threadIdx.x, lane = tid & 31, wid = tid >> 5;
    int bx = blockIdx.x;
    int v = bx / (NN / ROWS_PER_BLOCK);
    int rb = bx % (NN / ROWS_PER_BLOCK);
    int n0 = rb * ROWS_PER_BLOCK + wid * RPW;

    const float4* L4 = (const float4*)(lap + ((size_t)v * NN + n0) * (size_t)NN);
    const int ROW4 = NN / 4;

    unsigned long long acc[RPW][5];
#pragma unroll
    for (int r = 0; r < RPW; r++)
#pragma unroll
        for (int p = 0; p < 5; p++) acc[r][p] = 0ull;

    float4 a[RPW], b[RPW], cb[RPW];
    // preload steps 0 and 1 (overlap the first z fill)
#pragma unroll
    for (int r = 0; r < RPW; r++) a[r] = __ldcs(L4 + (size_t)r * ROW4 + lane);
#pragma unroll
    for (int r = 0; r < RPW; r++) b[r] = __ldcs(L4 + (size_t)r * ROW4 + 32 + lane);

    for (int c = 0; c < NCHUNK; c++) {
        __syncthreads();
        for (int i = tid; i < 5 * M_CHUNK; i += GEMV_THREADS) {
            int p = i >> 11;                  // 0..4
            int j = i & (M_CHUNK - 1);
            const float2* zp2 = (const float2*)(zsrc + (size_t)(c * M_CHUNK + j) * zstr + 2 * p);
            float2 zv = *zp2;
            zt[((j & 3) * 5 + p) * MQP + (j >> 2)] = pack2(zv.x, zv.y);
        }
        __syncthreads();

#pragma unroll 2
        for (int it = 0; it < ITS_PER_CHUNK; it++) {
            int s = c * ITS_PER_CHUNK + it;
            int sp = (s + 2 < NSTEPS) ? s + 2 : (NSTEPS - 1);
            // prefetch step s+2 (front-batched LDG.128 x8)
#pragma unroll
            for (int r = 0; r < RPW; r++)
                cb[r] = __ldcs(L4 + (size_t)r * ROW4 + sp * 32 + lane);

            int mi = it * 32 + lane;
#pragma unroll
            for (int q = 0; q < 4; q++) {
                unsigned long long zq[5];
#pragma unroll
                for (int p = 0; p < 5; p++) zq[p] = zt[(q * 5 + p) * MQP + mi];
#pragma unroll
                for (int r = 0; r < RPW; r++) {
                    float av = (q == 0) ? a[r].x : (q == 1) ? a[r].y : (q == 2) ? a[r].z : a[r].w;
                    unsigned long long d = pack2(av, av);
#pragma unroll
                    for (int p = 0; p < 5; p++) ffma2(acc[r][p], d, zq[p]);
                }
            }
#pragma unroll
            for (int r = 0; r < RPW; r++) { a[r] = b[r]; b[r] = cb[r]; }
        }
    }

#pragma unroll
    for (int r = 0; r < RPW; r++) {
        float vals[NK];
#pragma unroll
        for (int p = 0; p < 5; p++) {
            float2 f = unpack2(acc[r][p]);
            vals[2 * p] = f.x;
            vals[2 * p + 1] = f.y;
        }
#pragma unroll
        for (int k = 0; k < NK; k++)
            for (int s = 16; s; s >>= 1) vals[k] += __shfl_xor_sync(0xffffffffu, vals[k], s);
        if (lane == 0) {
            float* yr = g_Y + ((size_t)v * NN + n0 + r) * YP;
#pragma unroll
            for (int k = 0; k < NK; k++) yr[k] = vals[k];
        }
    }
}

// ---------------- kernel 3: softplus + DS combine + BN stats + BN + SELU (fused) ----------------
__device__ __forceinline__ float softplusf(float x) {
    return fmaxf(x, 0.0f) + __logf(1.0f + __expf(-fabsf(x)));
}

__device__ __forceinline__ void ds_comb(float* a1, const float* a2) {
    float S1 = 0.0f, S2 = 0.0f;
#pragma unroll
    for (int k = 0; k < NK; k++) { S1 += a1[k]; S2 += a2[k]; }
    float i1 = 1.0f / S1, i2 = 1.0f / S2;
    float u1 = (float)NK * i1, u2 = (float)NK * i2;
    float b1[NK], b2[NK];
    float sb1 = 0.0f, sb2 = 0.0f, dot = 0.0f;
#pragma unroll
    for (int k = 0; k < NK; k++) {
        b1[k] = (a1[k] - 1.0f) * i1;
        b2[k] = (a2[k] - 1.0f) * i2;
        sb1 += b1[k];
        sb2 += b2[k];
        dot += b1[k] * b2[k];
    }
    float C = sb1 * sb2 - dot;
    float invd = 1.0f / (1.0f - C);
    float Sn = (float)NK * (1.0f - C) / (u1 * u2);
#pragma unroll
    for (int k = 0; k < NK; k++)
        a1[k] = (b1[k] * b2[k] + b1[k] * u2 + b2[k] * u1) * invd * Sn + 1.0f;
}

__device__ __forceinline__ float seluf(float x) {
    const float sc = 1.0507009873554805f, al = 1.6732632423543772f;
    return x > 0.0f ? sc * x : sc * al * (__expf(x) - 1.0f);
}

#define CMB_THREADS 64
#define CMB_BLOCKS (NN / CMB_THREADS)   // 96 <= 148 SMs -> co-resident, spin is safe
__global__ __launch_bounds__(CMB_THREADS) void combine_bn_kernel(const float* __restrict__ z_ext,
                                                                 int use_ext, int t,
                                                                 float* __restrict__ out,
                                                                 const float* __restrict__ gamma,
                                                                 const float* __restrict__ beta,
                                                                 const float* __restrict__ theta) {
    const float* zsrc = use_ext ? z_ext : g_z;
    const int zstr = use_ext ? NK : YP;
    int n = blockIdx.x * CMB_THREADS + threadIdx.x;
    int lane = threadIdx.x & 31;

    float zn[NK];
#pragma unroll
    for (int p = 0; p < 5; p++) {
        float2 zv = *(const float2*)(zsrc + (size_t)n * zstr + 2 * p);
        zn[2 * p] = zv.x;
        zn[2 * p + 1] = zv.y;
    }

    float ac[NK];
#pragma unroll
    for (int v = 0; v < NV; v++) {
        const float4* y4 = (const float4*)(g_Y + ((size_t)v * NN + n) * YP);
        const float4* p4 = (const float4*)(g_proj + ((size_t)v * NN + n) * YP);
        float yv[12], pv[12];
#pragma unroll
        for (int q = 0; q < 3; q++) {
            float4 yq = y4[q];
            float4 pq = p4[q];
            yv[4 * q] = yq.x; yv[4 * q + 1] = yq.y; yv[4 * q + 2] = yq.z; yv[4 * q + 3] = yq.w;
            pv[4 * q] = pq.x; pv[4 * q + 1] = pq.y; pv[4 * q + 2] = pq.z; pv[4 * q + 3] = pq.w;
        }
        float av[NK];
#pragma unroll
        for (int k = 0; k < NK; k++) av[k] = softplusf(zn[k] - yv[k] + pv[k]) + 1.0f;
        if (v == 0) {
#pragma unroll
            for (int k = 0; k < NK; k++) ac[k] = av[k];
        } else {
            ds_comb(ac, av);
        }
    }

    // block-level stats reduction -> global atomics
    float rs[NK], rq[NK];
#pragma unroll
    for (int k = 0; k < NK; k++) { rs[k] = ac[k]; rq[k] = ac[k] * ac[k]; }
#pragma unroll
    for (int k = 0; k < NK; k++) {
        for (int s = 16; s; s >>= 1) {
            rs[k] += __shfl_xor_sync(0xffffffffu, rs[k], s);
            rq[k] += __shfl_xor_sync(0xffffffffu, rq[k], s);
        }
    }
    __shared__ float sh[2 * NK];
    if (threadIdx.x < 2 * NK) sh[threadIdx.x] = 0.0f;
    __syncthreads();
    if (lane == 0) {
#pragma unroll
        for (int k = 0; k < NK; k++) {
            atomicAdd(&sh[k], rs[k]);
            atomicAdd(&sh[NK + k], rq[k]);
        }
    }
    __syncthreads();
    if (threadIdx.x < 2 * NK)
        atomicAdd(&g_stats[t * 2 * NK + threadIdx.x], sh[threadIdx.x]);

    // grid-wide completion: all 96 blocks co-resident -> spin is deadlock-free
    __threadfence();
    __syncthreads();
    if (threadIdx.x == 0) {
        atomicAdd(&g_cnt[t], 1);
        while (atomicAdd(&g_cnt[t], 0) < CMB_BLOCKS) { __nanosleep(64); }
    }
    __syncthreads();
    __threadfence();

    // BN + SELU soft-threshold, h (= ac) still in registers
    float th = theta[0];
#pragma unroll
    for (int k = 0; k < NK; k++) {
        float mu = g_stats[t * 2 * NK + k] * (1.0f / NN);
        float ms = g_stats[t * 2 * NK + NK + k] * (1.0f / NN);
        float var = ms - mu * mu;
        float inv = rsqrtf(var + BN_EPS);
        float hn = (ac[k] - mu) * inv * gamma[k] + beta[k];
        float zz = seluf(hn - th) - seluf(-hn - th);
        out[(size_t)t * NN * NK + (size_t)n * NK + k] = zz;
        g_z[(size_t)n * YP + k] = zz;
    }
}

// ---------------- launcher ----------------
extern "C" void kernel_launch(void* const* d_in, const int* in_sizes, int n_in,
                              void* d_out, int out_size) {
    (void)in_sizes; (void)n_in; (void)out_size;
    const float* feat  = (const float*)d_in[0]; // [V,N,F]
    const float* lap   = (const float*)d_in[1]; // [V,N,N]
    const float* z0    = (const float*)d_in[2]; // [N,K]
    const float* U     = (const float*)d_in[3]; // [V,F,K]
    const float* theta = (const float*)d_in[4]; // [1]
    const float* gamma = (const float*)d_in[5]; // [K]
    const float* beta  = (const float*)d_in[6]; // [K]
    float* out = (float*)d_out;                 // [2,N,K]

    const int ZT_BYTES = 4 * 5 * MQP * 8;       // 82,240 B dynamic smem
    static int configured = 0;
    if (!configured) {
        cudaFuncSetAttribute(gemv_kernel, cudaFuncAttributeMaxDynamicSharedMemorySize, ZT_BYTES);
        configured = 1;
    }

    proj_kernel<<<NV * (NN / 8), 256>>>(feat, U);

    for (int t = 0; t < NITERS; t++) {
        int use_ext = (t == 0) ? 1 : 0;
        gemv_kernel<<<NV * (NN / ROWS_PER_BLOCK), GEMV_THREADS, ZT_BYTES>>>(lap, z0, use_ext);
        combine_bn_kernel<<<CMB_BLOCKS, CMB_THREADS>>>(z0, use_ext, t, out, gamma, beta, theta);
    }
}

// round 6
// speedup vs baseline: 1.5178x; 1.0631x over previous
#include <cuda_runtime.h>
#include <math.h>

#define NN 6144
#define NV 3
#define NF 512
#define NK 10
#define YP 12            // padded row stride for Y/proj/z scratch
#define NITERS 2
#define BN_EPS 1e-5f

#define M_CHUNK 1024
#define MQ (M_CHUNK / 4)         // 256
#define MQP (MQ + 2)             // 258 (padded)
#define NCHUNK (NN / M_CHUNK)          // 6
#define ITS_PER_CHUNK (M_CHUNK / 128)  // 8
#define NSTEPS (NN / 128)              // 48

// ---------------- scratch (device globals, no allocation) ----------------
__device__ float g_proj[NV * NN * YP];
__device__ float g_Y[NV * NN * YP];
__device__ float g_z[NN * YP];
__device__ float g_stats[NITERS * 2 * NK];
__device__ int   g_cnt[NITERS];

// ---------------- packed f32x2 helpers ----------------
__device__ __forceinline__ unsigned long long pack2(float a, float b) {
    unsigned long long r;
    asm("mov.b64 %0, {%1, %2};" : "=l"(r) : "f"(a), "f"(b));
    return r;
}
__device__ __forceinline__ void ffma2(unsigned long long& d, unsigned long long a, unsigned long long b) {
    asm("fma.rn.f32x2 %0, %1, %2, %0;" : "+l"(d) : "l"(a), "l"(b));
}
__device__ __forceinline__ float2 unpack2(unsigned long long v) {
    float2 r;
    asm("mov.b64 {%0, %1}, %2;" : "=f"(r.x), "=f"(r.y) : "l"(v));
    return r;
}

// ---------------- kernel 1: proj (also zeroes stats + counters) ----------------
__global__ __launch_bounds__(256) void proj_kernel(const float* __restrict__ feat,
                                                   const float* __restrict__ U) {
    __shared__ float Ut[NK][NF];
    int tid = threadIdx.x, lane = tid & 31, wid = tid >> 5;
    int bx = blockIdx.x;
    if (bx == 0) {
        if (tid < NITERS * 2 * NK) g_stats[tid] = 0.0f;
        if (tid >= 64 && tid < 64 + NITERS) g_cnt[tid - 64] = 0;
    }

    int v = bx / (NN / 8);
    int rb = bx % (NN / 8);

    for (int i = tid; i < NF * NK; i += 256) {
        int f = i / NK, k = i % NK;
        Ut[k][f] = U[(size_t)v * NF * NK + i];
    }
    __syncthreads();

    int n = rb * 8 + wid;
    const float4* xr = (const float4*)(feat + ((size_t)v * NN + n) * NF);
    float acc[NK];
#pragma unroll
    for (int k = 0; k < NK; k++) acc[k] = 0.0f;

#pragma unroll
    for (int it = 0; it < NF / 128; it++) {
        int f4 = it * 32 + lane;
        float4 x = xr[f4];
#pragma unroll
        for (int k = 0; k < NK; k++) {
            float4 u = *(const float4*)&Ut[k][f4 * 4];
            acc[k] = fmaf(x.x, u.x, acc[k]);
            acc[k] = fmaf(x.y, u.y, acc[k]);
            acc[k] = fmaf(x.z, u.z, acc[k]);
            acc[k] = fmaf(x.w, u.w, acc[k]);
        }
    }
#pragma unroll
    for (int k = 0; k < NK; k++)
        for (int s = 16; s; s >>= 1) acc[k] += __shfl_xor_sync(0xffffffffu, acc[k], s);

    if (lane == 0) {
        float* pr = g_proj + ((size_t)v * NN + n) * YP;
#pragma unroll
        for (int k = 0; k < NK; k++) pr[k] = acc[k];
    }
}

// ---------------- kernel 2: Y[v,n,k] = sum_m L[v,n,m] * z[m,k] ----------------
// 256 threads, 2 CTAs/SM (regs ~118 < 128 cap), 4 rows/warp, LDG.128,
// depth-2 register pipeline (8 LDG.128 in flight / warp = 4 KB).
// z chunk packed as u64 k-pairs in smem (conflict-free LDS.64).
#define GEMV_THREADS 256
#define RPW 4
#define ROWS_PER_BLOCK 32    // 8 warps * 4 rows

__global__ __launch_bounds__(GEMV_THREADS, 2) void gemv_kernel(const float* __restrict__ lap,
                                                               const float* __restrict__ z_ext,
                                                               int use_ext) {
    const float* zsrc = use_ext ? z_ext : g_z;
    const int zstr = use_ext ? NK : YP;
    __shared__ unsigned long long zt[4 * 5 * MQP];   // 41,280 B

    int tid = threadIdx.x, lane = tid & 31, wid = tid >> 5;
    int bx = blockIdx.x;
    int v = bx / (NN / ROWS_PER_BLOCK);
    int rb = bx % (NN / ROWS_PER_BLOCK);
    int n0 = rb * ROWS_PER_BLOCK + wid * RPW;

    const float4* L4 = (const float4*)(lap + ((size_t)v * NN + n0) * (size_t)NN);
    const int ROW4 = NN / 4;

    unsigned long long acc[RPW][5];
#pragma unroll
    for (int r = 0; r < RPW; r++)
#pragma unroll
        for (int p = 0; p < 5; p++) acc[r][p] = 0ull;

    float4 a[RPW], b[RPW], cb[RPW];
    // preload steps 0 and 1 (overlap the first z fill)
#pragma unroll
    for (int r = 0; r < RPW; r++) a[r] = __ldcs(L4 + (size_t)r * ROW4 + lane);
#pragma unroll
    for (int r = 0; r < RPW; r++) b[r] = __ldcs(L4 + (size_t)r * ROW4 + 32 + lane);

    for (int c = 0; c < NCHUNK; c++) {
        __syncthreads();
        for (int i = tid; i < 5 * M_CHUNK; i += GEMV_THREADS) {
            int p = i >> 10;                  // 0..4
            int j = i & (M_CHUNK - 1);
            const float2* zp2 = (const float2*)(zsrc + (size_t)(c * M_CHUNK + j) * zstr + 2 * p);
            float2 zv = *zp2;
            zt[((j & 3) * 5 + p) * MQP + (j >> 2)] = pack2(zv.x, zv.y);
        }
        __syncthreads();

#pragma unroll 2
        for (int it = 0; it < ITS_PER_CHUNK; it++) {
            int s = c * ITS_PER_CHUNK + it;
            int sp = (s + 2 < NSTEPS) ? s + 2 : (NSTEPS - 1);
            // prefetch step s+2 (front-batched LDG.128 x4)
#pragma unroll
            for (int r = 0; r < RPW; r++)
                cb[r] = __ldcs(L4 + (size_t)r * ROW4 + sp * 32 + lane);

            int mi = it * 32 + lane;
#pragma unroll
            for (int q = 0; q < 4; q++) {
                unsigned long long zq[5];
#pragma unroll
                for (int p = 0; p < 5; p++) zq[p] = zt[(q * 5 + p) * MQP + mi];
#pragma unroll
                for (int r = 0; r < RPW; r++) {
                    float av = (q == 0) ? a[r].x : (q == 1) ? a[r].y : (q == 2) ? a[r].z : a[r].w;
                    unsigned long long d = pack2(av, av);
#pragma unroll
                    for (int p = 0; p < 5; p++) ffma2(acc[r][p], d, zq[p]);
                }
            }
#pragma unroll
            for (int r = 0; r < RPW; r++) { a[r] = b[r]; b[r] = cb[r]; }
        }
    }

#pragma unroll
    for (int r = 0; r < RPW; r++) {
        float vals[NK];
#pragma unroll
        for (int p = 0; p < 5; p++) {
            float2 f = unpack2(acc[r][p]);
            vals[2 * p] = f.x;
            vals[2 * p + 1] = f.y;
        }
#pragma unroll
        for (int k = 0; k < NK; k++)
            for (int s = 16; s; s >>= 1) vals[k] += __shfl_xor_sync(0xffffffffu, vals[k], s);
        if (lane == 0) {
            float* yr = g_Y + ((size_t)v * NN + n0 + r) * YP;
#pragma unroll
            for (int k = 0; k < NK; k++) yr[k] = vals[k];
        }
    }
}

// ---------------- kernel 3: softplus + DS combine + BN stats + BN + SELU (fused) ----------------
__device__ __forceinline__ float softplusf(float x) {
    return fmaxf(x, 0.0f) + __logf(1.0f + __expf(-fabsf(x)));
}

__device__ __forceinline__ void ds_comb(float* a1, const float* a2) {
    float S1 = 0.0f, S2 = 0.0f;
#pragma unroll
    for (int k = 0; k < NK; k++) { S1 += a1[k]; S2 += a2[k]; }
    float i1 = 1.0f / S1, i2 = 1.0f / S2;
    float u1 = (float)NK * i1, u2 = (float)NK * i2;
    float b1[NK], b2[NK];
    float sb1 = 0.0f, sb2 = 0.0f, dot = 0.0f;
#pragma unroll
    for (int k = 0; k < NK; k++) {
        b1[k] = (a1[k] - 1.0f) * i1;
        b2[k] = (a2[k] - 1.0f) * i2;
        sb1 += b1[k];
        sb2 += b2[k];
        dot += b1[k] * b2[k];
    }
    float C = sb1 * sb2 - dot;
    float invd = 1.0f / (1.0f - C);
    float Sn = (float)NK * (1.0f - C) / (u1 * u2);
#pragma unroll
    for (int k = 0; k < NK; k++)
        a1[k] = (b1[k] * b2[k] + b1[k] * u2 + b2[k] * u1) * invd * Sn + 1.0f;
}

__device__ __forceinline__ float seluf(float x) {
    const float sc = 1.0507009873554805f, al = 1.6732632423543772f;
    return x > 0.0f ? sc * x : sc * al * (__expf(x) - 1.0f);
}

#define CMB_THREADS 64
#define CMB_BLOCKS (NN / CMB_THREADS)   // 96 <= 148 SMs -> co-resident, spin is safe
__global__ __launch_bounds__(CMB_THREADS) void combine_bn_kernel(const float* __restrict__ z_ext,
                                                                 int use_ext, int t,
                                                                 float* __restrict__ out,
                                                                 const float* __restrict__ gamma,
                                                                 const float* __restrict__ beta,
                                                                 const float* __restrict__ theta) {
    const float* zsrc = use_ext ? z_ext : g_z;
    const int zstr = use_ext ? NK : YP;
    int n = blockIdx.x * CMB_THREADS + threadIdx.x;
    int lane = threadIdx.x & 31;

    float zn[NK];
#pragma unroll
    for (int p = 0; p < 5; p++) {
        float2 zv = *(const float2*)(zsrc + (size_t)n * zstr + 2 * p);
        zn[2 * p] = zv.x;
        zn[2 * p + 1] = zv.y;
    }

    float ac[NK];
#pragma unroll
    for (int v = 0; v < NV; v++) {
        const float4* y4 = (const float4*)(g_Y + ((size_t)v * NN + n) * YP);
        const float4* p4 = (const float4*)(g_proj + ((size_t)v * NN + n) * YP);
        float yv[12], pv[12];
#pragma unroll
        for (int q = 0; q < 3; q++) {
            float4 yq = y4[q];
            float4 pq = p4[q];
            yv[4 * q] = yq.x; yv[4 * q + 1] = yq.y; yv[4 * q + 2] = yq.z; yv[4 * q + 3] = yq.w;
            pv[4 * q] = pq.x; pv[4 * q + 1] = pq.y; pv[4 * q + 2] = pq.z; pv[4 * q + 3] = pq.w;
        }
        float av[NK];
#pragma unroll
        for (int k = 0; k < NK; k++) av[k] = softplusf(zn[k] - yv[k] + pv[k]) + 1.0f;
        if (v == 0) {
#pragma unroll
            for (int k = 0; k < NK; k++) ac[k] = av[k];
        } else {
            ds_comb(ac, av);
        }
    }

    // block-level stats reduction -> global atomics
    float rs[NK], rq[NK];
#pragma unroll
    for (int k = 0; k < NK; k++) { rs[k] = ac[k]; rq[k] = ac[k] * ac[k]; }
#pragma unroll
    for (int k = 0; k < NK; k++) {
        for (int s = 16; s; s >>= 1) {
            rs[k] += __shfl_xor_sync(0xffffffffu, rs[k], s);
            rq[k] += __shfl_xor_sync(0xffffffffu, rq[k], s);
        }
    }
    __shared__ float sh[2 * NK];
    if (threadIdx.x < 2 * NK) sh[threadIdx.x] = 0.0f;
    __syncthreads();
    if (lane == 0) {
#pragma unroll
        for (int k = 0; k < NK; k++) {
            atomicAdd(&sh[k], rs[k]);
            atomicAdd(&sh[NK + k], rq[k]);
        }
    }
    __syncthreads();
    if (threadIdx.x < 2 * NK)
        atomicAdd(&g_stats[t * 2 * NK + threadIdx.x], sh[threadIdx.x]);

    // grid-wide completion: all 96 blocks co-resident -> spin is deadlock-free
    __threadfence();
    __syncthreads();
    if (threadIdx.x == 0) {
        atomicAdd(&g_cnt[t], 1);
        while (atomicAdd(&g_cnt[t], 0) < CMB_BLOCKS) { __nanosleep(64); }
    }
    __syncthreads();
    __threadfence();

    // BN + SELU soft-threshold, h (= ac) still in registers
    float th = theta[0];
#pragma unroll
    for (int k = 0; k < NK; k++) {
        float mu = g_stats[t * 2 * NK + k] * (1.0f / NN);
        float ms = g_stats[t * 2 * NK + NK + k] * (1.0f / NN);
        float var = ms - mu * mu;
        float inv = rsqrtf(var + BN_EPS);
        float hn = (ac[k] - mu) * inv * gamma[k] + beta[k];
        float zz = seluf(hn - th) - seluf(-hn - th);
        out[(size_t)t * NN * NK + (size_t)n * NK + k] = zz;
        g_z[(size_t)n * YP + k] = zz;
    }
}

// ---------------- launcher ----------------
extern "C" void kernel_launch(void* const* d_in, const int* in_sizes, int n_in,
                              void* d_out, int out_size) {
    (void)in_sizes; (void)n_in; (void)out_size;
    const float* feat  = (const float*)d_in[0]; // [V,N,F]
    const float* lap   = (const float*)d_in[1]; // [V,N,N]
    const float* z0    = (const float*)d_in[2]; // [N,K]
    const float* U     = (const float*)d_in[3]; // [V,F,K]
    const float* theta = (const float*)d_in[4]; // [1]
    const float* gamma = (const float*)d_in[5]; // [K]
    const float* beta  = (const float*)d_in[6]; // [K]
    float* out = (float*)d_out;                 // [2,N,K]

    proj_kernel<<<NV * (NN / 8), 256>>>(feat, U);

    for (int t = 0; t < NITERS; t++) {
        int use_ext = (t == 0) ? 1 : 0;
        gemv_kernel<<<NV * (NN / ROWS_PER_BLOCK), GEMV_THREADS>>>(lap, z0, use_ext);
        combine_bn_kernel<<<CMB_BLOCKS, CMB_THREADS>>>(z0, use_ext, t, out, gamma, beta, theta);
    }
}